// round 3
// baseline (speedup 1.0000x reference)
#include <cuda_runtime.h>
#include <math.h>

// Problem constants
#define NV 50000
#define NE 640000
#define NHALF 320000
#define NTILES (NE/64)        // 10000
#define HALF_TILES (NHALF/64) // 5000
#define R2 474                // 2*NREL
#define FIN 128
#define FOUT 128
#define CSTR 132              // padded smem row stride

// ---------------- scratch (device globals; no allocation allowed) ----------
__device__ float g_hacc[(size_t)NV * FOUT];   // atomic accumulation: segment_sum(msg*norm)
__device__ float g_h2[(size_t)NV * FOUT];     // pre-batchnorm activations
__device__ float g_Qin[FIN * FOUT];           // node_rel_w folded with in_w
__device__ float g_Qout[FIN * FOUT];          // node_rel_w folded with out_w
__device__ float g_w1a[FIN * 4];              // node_rel_w folded with att_w[0:32]
__device__ float g_w2a[FIN * 4];              // node_w    folded with att_w[32:64]
__device__ float g_sum[FOUT];                 // batchnorm channel sums
__device__ float g_sumsq[FOUT];               // batchnorm channel sum of squares

// ---------------- kernel 0: zero scratch -----------------------------------
__global__ void zero_kernel() {
    int idx = blockIdx.x * blockDim.x + threadIdx.x;
    const int n4 = NV * FOUT / 4;
    float4 z = make_float4(0.f, 0.f, 0.f, 0.f);
    for (int i = idx; i < n4; i += gridDim.x * blockDim.x)
        ((float4*)g_hacc)[i] = z;
    if (idx < FOUT) { g_sum[idx] = 0.f; g_sumsq[idx] = 0.f; }
}

// ---------------- kernel 1a: fold attention weights -------------------------
// w1a[i,k] = sum_d node_rel_w[k,i,d] * att_w[d]      (edge_data part of cat)
// w2a[i,k] = sum_d node_w[k,i,d]     * att_w[32+d]   (node_data part of cat)
__global__ void wfold_kernel(const float* __restrict__ node_w,
                             const float* __restrict__ node_rel_w,
                             const float* __restrict__ att_w) {
    int i = threadIdx.x;   // 0..127
    if (i >= 128) return;
#pragma unroll
    for (int k = 0; k < 4; k++) {
        float s1 = 0.f, s2 = 0.f;
#pragma unroll
        for (int d = 0; d < 32; d++) {
            s1 = fmaf(node_rel_w[k * 4096 + i * 32 + d], att_w[d], s1);
            s2 = fmaf(node_w[k * 4096 + i * 32 + d], att_w[32 + d], s2);
        }
        g_w1a[i * 4 + k] = s1;
        g_w2a[i * 4 + k] = s2;
    }
}

// ---------------- kernel 1b: fold projection weights -------------------------
// Qin[i, k*32+o]  = sum_d node_rel_w[k,i,d] * in_w[k,d,o]
// Qout[i, k*32+o] = sum_d node_rel_w[k,i,d] * out_w[k,d,o]
__global__ void qfold_kernel(const float* __restrict__ node_rel_w,
                             const float* __restrict__ in_w,
                             const float* __restrict__ out_w) {
    __shared__ float nrw_s[128];  // [k][d] for this feature i
    int i = blockIdx.x;
    int tid = threadIdx.x;
    {
        int k = tid >> 5, d = tid & 31;
        nrw_s[tid] = node_rel_w[k * 4096 + i * 32 + d];
    }
    __syncthreads();

    int k = tid >> 5, o = tid & 31;
    float qi = 0.f, qo = 0.f;
#pragma unroll
    for (int d = 0; d < 32; d++) {
        float w = nrw_s[k * 32 + d];
        qi = fmaf(w, in_w[k * 1024 + d * 32 + o], qi);
        qo = fmaf(w, out_w[k * 1024 + d * 32 + o], qo);
    }
    g_Qin[i * 128 + tid] = qi;
    g_Qout[i * 128 + tid] = qo;
}

// ---------------- kernel 2: fused edge kernel --------------------------------
__global__ void __launch_bounds__(128) edge_kernel(
    const float* __restrict__ node_repr, const float* __restrict__ rel_repr,
    const int* __restrict__ src, const int* __restrict__ dst,
    const int* __restrict__ etype, const float* __restrict__ nrm) {
    extern __shared__ float sm[];
    float* Qs      = sm;                     // 16384
    float* comp    = Qs + 16384;             // 64*CSTR = 8448
    float* xdst    = comp + 64 * CSTR;       // 8448
    float* w1s     = xdst + 64 * CSTR;       // 512
    float* w2s     = w1s + 512;              // 512
    float* s_scale = w2s + 512;              // 256
    float* s_nrm   = s_scale + 256;          // 64
    int*   s_src   = (int*)(s_nrm + 64);     // 64
    int*   s_dst   = s_src + 64;             // 64
    int*   s_et    = s_dst + 64;             // 64

    int tid = threadIdx.x;
    int tile = blockIdx.x;
    int e0 = tile * 64;
    const float* Q = (tile < HALF_TILES) ? g_Qin : g_Qout;

    // ---- phase A: stage weights + indices ----
    {
        const float4* Qg = (const float4*)Q;
        float4* Qs4 = (float4*)Qs;
#pragma unroll
        for (int q = 0; q < 32; q++) Qs4[tid + q * 128] = Qg[tid + q * 128];
    }
    for (int q = tid; q < 512; q += 128) {
        w1s[q] = g_w1a[q];
        w2s[q] = g_w2a[q];
    }
    if (tid < 64) {
        s_src[tid] = src[e0 + tid];
        s_dst[tid] = dst[e0 + tid];
        s_et[tid]  = etype[e0 + tid];
        s_nrm[tid] = nrm[e0 + tid];
    }
    __syncthreads();

    // ---- phase B: gather comp + x_dst (2 threads per edge) ----
    int e = tid >> 1;
    int h = tid & 1;
    int ioff = h * 64;
    {
        const float4* xs = (const float4*)(node_repr + (size_t)s_src[e] * 128 + ioff);
        const float4* rr = (const float4*)(rel_repr  + (size_t)s_et[e]  * 128 + ioff);
        const float4* xd = (const float4*)(node_repr + (size_t)s_dst[e] * 128 + ioff);
        float* cp = comp + e * CSTR + ioff;
        float* dp = xdst + e * CSTR + ioff;
#pragma unroll
        for (int q = 0; q < 16; q++) {
            float4 a = xs[q], r = rr[q], d4 = xd[q];
            float4 c;
            c.x = a.x * r.x; c.y = a.y * r.y; c.z = a.z * r.z; c.w = a.w * r.w;
            *(float4*)(cp + q * 4) = c;
            *(float4*)(dp + q * 4) = d4;
        }
    }
    __syncthreads();

    // ---- phase C: logits + softmax; fold norm (NOT /3 — applied in node kernel) ----
    {
        float lg0 = 0.f, lg1 = 0.f, lg2 = 0.f, lg3 = 0.f;
        const float* cp = comp + e * CSTR;
        const float* dp = xdst + e * CSTR;
#pragma unroll 4
        for (int i = 0; i < 64; i++) {
            int ii = ioff + i;
            float cv = cp[ii];
            float dv = dp[ii];
            lg0 = fmaf(cv, w1s[ii * 4 + 0], lg0);
            lg1 = fmaf(cv, w1s[ii * 4 + 1], lg1);
            lg2 = fmaf(cv, w1s[ii * 4 + 2], lg2);
            lg3 = fmaf(cv, w1s[ii * 4 + 3], lg3);
            lg0 = fmaf(dv, w2s[ii * 4 + 0], lg0);
            lg1 = fmaf(dv, w2s[ii * 4 + 1], lg1);
            lg2 = fmaf(dv, w2s[ii * 4 + 2], lg2);
            lg3 = fmaf(dv, w2s[ii * 4 + 3], lg3);
        }
        lg0 += __shfl_xor_sync(0xFFFFFFFFu, lg0, 1);
        lg1 += __shfl_xor_sync(0xFFFFFFFFu, lg1, 1);
        lg2 += __shfl_xor_sync(0xFFFFFFFFu, lg2, 1);
        lg3 += __shfl_xor_sync(0xFFFFFFFFu, lg3, 1);
        if (h == 0) {
            float l0 = fmaxf(lg0, 0.f);
            float l1 = fmaxf(lg1, 0.f);
            float l2 = fmaxf(lg2, 0.f);
            float l3 = fmaxf(lg3, 0.f);
            float e0x = expf(l0), e1x = expf(l1), e2x = expf(l2), e3x = expf(l3);
            float inv = s_nrm[e] / (e0x + e1x + e2x + e3x);   // FIX: no /3 here
            s_scale[e * 4 + 0] = e0x * inv;
            s_scale[e * 4 + 1] = e1x * inv;
            s_scale[e * 4 + 2] = e2x * inv;
            s_scale[e * 4 + 3] = e3x * inv;
        }
    }
    __syncthreads();

    // ---- phase D: GEMM 64x128x128, thread tile 8 edges x 8 cols ----
    int c = tid & 15, r = tid >> 4;
    float acc[8][8];
#pragma unroll
    for (int u = 0; u < 8; u++)
#pragma unroll
        for (int m = 0; m < 8; m++) acc[u][m] = 0.f;

    const float* ap = comp + (r * 8) * CSTR;
    const float* bp = Qs + c;
#pragma unroll 1
    for (int i = 0; i < 128; i += 4) {
#pragma unroll
        for (int ii = 0; ii < 4; ii++) {
            float bv[8];
#pragma unroll
            for (int m = 0; m < 8; m++) bv[m] = bp[(i + ii) * 128 + m * 16];
#pragma unroll
            for (int u = 0; u < 8; u++) {
                float av = ap[u * CSTR + i + ii];
#pragma unroll
                for (int m = 0; m < 8; m++) acc[u][m] = fmaf(av, bv[m], acc[u][m]);
            }
        }
    }

    // ---- phase E: scatter hacc[dst] += scale[e,k] * acc ----
#pragma unroll
    for (int u = 0; u < 8; u++) {
        int ee = r * 8 + u;
        float* hp = g_hacc + (size_t)s_dst[ee] * 128;
        const float* sc = s_scale + ee * 4;
#pragma unroll
        for (int m = 0; m < 8; m++) {
            int j = c + m * 16;
            atomicAdd(hp + j, acc[u][m] * sc[j >> 5]);
        }
    }
}

// ---------------- kernel 3: node kernel (self-loop GEMM, writes g_h2) -------
// h = hacc/3;  g_h2 = h + (h*loop_rel)@loop_w/3 + bias
__global__ void __launch_bounds__(128) node_kernel(
    const float* __restrict__ loop_rel, const float* __restrict__ loop_w,
    const float* __restrict__ bias) {
    extern __shared__ float sm[];
    float* Ws = sm;                 // 16384
    float* t  = Ws + 16384;         // 64*CSTR
    float* sh = t + 64 * CSTR;      // 64*CSTR

    int tid = threadIdx.x;
    int row0 = blockIdx.x * 64;

    {
        const float4* Wg = (const float4*)loop_w;
        float4* Ws4 = (float4*)Ws;
#pragma unroll
        for (int q = 0; q < 32; q++) Ws4[tid + q * 128] = Wg[tid + q * 128];
    }

    // stage h = hacc/3 and t = h * loop_rel
    {
        int e = tid >> 1;
        int ioff = (tid & 1) * 64;
        int row = row0 + e;
        float* tp = t + e * CSTR + ioff;
        float* hp = sh + e * CSTR + ioff;
        if (row < NV) {
            const float4* hv4 = (const float4*)(g_hacc + (size_t)row * 128 + ioff);
            const float4* lr4 = (const float4*)(loop_rel + ioff);
#pragma unroll
            for (int q = 0; q < 16; q++) {
                float4 hh = hv4[q];
                hh.x *= (1.f / 3.f); hh.y *= (1.f / 3.f); hh.z *= (1.f / 3.f); hh.w *= (1.f / 3.f);
                *(float4*)(hp + q * 4) = hh;
                float4 lr = lr4[q];
                float4 tv;
                tv.x = hh.x * lr.x; tv.y = hh.y * lr.y; tv.z = hh.z * lr.z; tv.w = hh.w * lr.w;
                *(float4*)(tp + q * 4) = tv;
            }
        } else {
            float4 z = make_float4(0.f, 0.f, 0.f, 0.f);
#pragma unroll
            for (int q = 0; q < 16; q++) {
                *(float4*)(hp + q * 4) = z;
                *(float4*)(tp + q * 4) = z;
            }
        }
    }
    __syncthreads();

    int c = tid & 15, r = tid >> 4;
    float acc[8][8];
#pragma unroll
    for (int u = 0; u < 8; u++)
#pragma unroll
        for (int m = 0; m < 8; m++) acc[u][m] = 0.f;

    const float* ap = t + (r * 8) * CSTR;
    const float* bp = Ws + c;
#pragma unroll 1
    for (int i = 0; i < 128; i += 4) {
#pragma unroll
        for (int ii = 0; ii < 4; ii++) {
            float bv[8];
#pragma unroll
            for (int m = 0; m < 8; m++) bv[m] = bp[(i + ii) * 128 + m * 16];
#pragma unroll
            for (int u = 0; u < 8; u++) {
                float av = ap[u * CSTR + i + ii];
#pragma unroll
                for (int m = 0; m < 8; m++) acc[u][m] = fmaf(av, bv[m], acc[u][m]);
            }
        }
    }

#pragma unroll
    for (int u = 0; u < 8; u++) {
        int e = r * 8 + u;
        int row = row0 + e;
        if (row < NV) {
#pragma unroll
            for (int m = 0; m < 8; m++) {
                int j = c + m * 16;
                float v = sh[e * CSTR + j] + acc[u][m] * (1.f / 3.f) + bias[j];
                g_h2[(size_t)row * 128 + j] = v;
            }
        }
    }
}

// ---------------- kernel 3b: BN statistics over g_h2 -------------------------
__global__ void bnstats_kernel() {
    __shared__ float s1s[128], s2s[128];
    int tid = threadIdx.x;
    int c = tid & 127;
    int half = tid >> 7;
    int row0 = blockIdx.x * 128;

    float s1 = 0.f, s2 = 0.f;
#pragma unroll 4
    for (int i = 0; i < 64; i++) {
        int row = row0 + half + 2 * i;
        if (row < NV) {
            float v = g_h2[(size_t)row * 128 + c];
            s1 += v;
            s2 = fmaf(v, v, s2);
        }
    }
    if (half == 1) { s1s[c] = s1; s2s[c] = s2; }
    __syncthreads();
    if (half == 0) {
        atomicAdd(&g_sum[c], s1 + s1s[c]);
        atomicAdd(&g_sumsq[c], s2 + s2s[c]);
    }
}

// ---------------- kernel 4: batchnorm + tanh ---------------------------------
__global__ void finalize_kernel(const float* __restrict__ gamma,
                                const float* __restrict__ beta,
                                float* __restrict__ out) {
    __shared__ float sa[128], sb[128];
    int tid = threadIdx.x;
    if (tid < 128) {
        float mean = g_sum[tid] * (1.f / NV);
        float var = g_sumsq[tid] * (1.f / NV) - mean * mean;
        float a = gamma[tid] * rsqrtf(var + 1e-5f);
        sa[tid] = a;
        sb[tid] = beta[tid] - mean * a;
    }
    __syncthreads();
    const int n4 = NV * FOUT / 4;
    for (int i = blockIdx.x * blockDim.x + tid; i < n4; i += gridDim.x * blockDim.x) {
        float4 v = ((const float4*)g_h2)[i];
        int c0 = (i * 4) & 127;
        float4 y;
        y.x = tanhf(fmaf(v.x, sa[c0 + 0], sb[c0 + 0]));
        y.y = tanhf(fmaf(v.y, sa[c0 + 1], sb[c0 + 1]));
        y.z = tanhf(fmaf(v.z, sa[c0 + 2], sb[c0 + 2]));
        y.w = tanhf(fmaf(v.w, sa[c0 + 3], sb[c0 + 3]));
        ((float4*)out)[i] = y;
    }
}

// ---------------- kernel 5: rel_out = rel_repr @ w_rel -----------------------
__global__ void relout_kernel(const float* __restrict__ rel_repr,
                              const float* __restrict__ w_rel,
                              float* __restrict__ out) {
    __shared__ float rrow[128];
    int b = blockIdx.x, tid = threadIdx.x;
    rrow[tid] = rel_repr[b * 128 + tid];
    __syncthreads();
    float s = 0.f;
#pragma unroll 4
    for (int i = 0; i < 128; i++) s = fmaf(rrow[i], w_rel[i * 128 + tid], s);
    out[(size_t)NV * FOUT + b * 128 + tid] = s;
}

// ---------------- host launcher ----------------------------------------------
extern "C" void kernel_launch(void* const* d_in, const int* in_sizes, int n_in,
                              void* d_out, int out_size) {
    const float* node_repr  = (const float*)d_in[0];
    const float* rel_repr   = (const float*)d_in[1];
    const int*   src        = (const int*)d_in[2];
    const int*   dst        = (const int*)d_in[3];
    const int*   etype      = (const int*)d_in[4];
    const float* nrm        = (const float*)d_in[5];
    const float* node_w     = (const float*)d_in[6];
    const float* node_rel_w = (const float*)d_in[7];
    const float* in_w       = (const float*)d_in[8];
    const float* out_w      = (const float*)d_in[9];
    const float* att_w      = (const float*)d_in[10];
    const float* loop_rel   = (const float*)d_in[11];
    const float* loop_w     = (const float*)d_in[12];
    const float* w_rel      = (const float*)d_in[13];
    const float* bias       = (const float*)d_in[14];
    const float* bn_gamma   = (const float*)d_in[15];
    const float* bn_beta    = (const float*)d_in[16];
    float* out = (float*)d_out;

    static const int EDGE_SMEM = (16384 + 2 * 64 * CSTR + 512 + 512 + 256 + 64 + 192) * 4;
    static const int NODE_SMEM = (16384 + 2 * 64 * CSTR) * 4;
    cudaFuncSetAttribute(edge_kernel, cudaFuncAttributeMaxDynamicSharedMemorySize, EDGE_SMEM);
    cudaFuncSetAttribute(node_kernel, cudaFuncAttributeMaxDynamicSharedMemorySize, NODE_SMEM);

    zero_kernel<<<512, 256>>>();
    wfold_kernel<<<1, 128>>>(node_w, node_rel_w, att_w);
    qfold_kernel<<<128, 128>>>(node_rel_w, in_w, out_w);
    edge_kernel<<<NTILES, 128, EDGE_SMEM>>>(node_repr, rel_repr, src, dst, etype, nrm);
    node_kernel<<<(NV + 63) / 64, 128, NODE_SMEM>>>(loop_rel, loop_w, bias);
    bnstats_kernel<<<(NV + 127) / 128, 256>>>();
    finalize_kernel<<<1024, 256>>>(bn_gamma, bn_beta, out);
    relout_kernel<<<R2, 128>>>(rel_repr, w_rel, out);
}